// round 1
// baseline (speedup 1.0000x reference)
#include <cuda_runtime.h>
#include <cuda_bf16.h>
#include <math_constants.h>

// Problem constants
#define BATCH 2
#define SEQ   2048
#define EMB   1024
#define HEADS 16
#define HDIM  64
#define ROWS  (BATCH * SEQ)   // 4096

// Scratch (allocation-free rule: __device__ globals)
__device__ float g_Q[ROWS * EMB];    // [B*S, E]  (per-head Q, layout row = b*S+s, col = h*D+d)
__device__ float g_K[ROWS * HDIM];   // [B*S, D]
__device__ float g_V[ROWS * HDIM];   // [B*S, D]

// ---------------------------------------------------------------------------
// SGEMM: C[M,N] = A[M,K] @ B[K,N], all row-major. 64x64 block tile, BK=16,
// 256 threads (16x16), 4x4 register tile per thread. M,N,K multiples of 64/16.
// ---------------------------------------------------------------------------
__global__ __launch_bounds__(256) void sgemm64(
    const float* __restrict__ A, const float* __restrict__ B, float* __restrict__ C,
    int M, int N, int K)
{
    __shared__ float As[16][65];   // As[k][m]
    __shared__ float Bs[16][65];   // Bs[k][n]

    const int tid = threadIdx.x;
    const int tx = tid & 15;
    const int ty = tid >> 4;
    const int m0 = blockIdx.y * 64;
    const int n0 = blockIdx.x * 64;

    float acc[4][4];
#pragma unroll
    for (int i = 0; i < 4; i++)
#pragma unroll
        for (int j = 0; j < 4; j++) acc[i][j] = 0.0f;

    for (int kk = 0; kk < K; kk += 16) {
        // Load A tile 64x16 -> As[k][m] (transposed store)
#pragma unroll
        for (int i = 0; i < 4; i++) {
            int e = tid * 4 + i;
            int r = e >> 4, c = e & 15;
            As[c][r] = A[(size_t)(m0 + r) * K + kk + c];
        }
        // Load B tile 16x64 -> Bs[k][n]
#pragma unroll
        for (int i = 0; i < 4; i++) {
            int e = tid * 4 + i;
            int r = e >> 6, c = e & 63;
            Bs[r][c] = B[(size_t)(kk + r) * N + n0 + c];
        }
        __syncthreads();

#pragma unroll
        for (int k = 0; k < 16; k++) {
            float a[4], b[4];
#pragma unroll
            for (int i = 0; i < 4; i++) a[i] = As[k][ty * 4 + i];
#pragma unroll
            for (int j = 0; j < 4; j++) b[j] = Bs[k][tx * 4 + j];
#pragma unroll
            for (int i = 0; i < 4; i++)
#pragma unroll
                for (int j = 0; j < 4; j++) acc[i][j] = fmaf(a[i], b[j], acc[i][j]);
        }
        __syncthreads();
    }

#pragma unroll
    for (int i = 0; i < 4; i++) {
        int row = m0 + ty * 4 + i;
#pragma unroll
        for (int j = 0; j < 4; j++) {
            C[(size_t)row * N + n0 + tx * 4 + j] = acc[i][j];
        }
    }
}

// ---------------------------------------------------------------------------
// Flash attention (causal, multi-query: K/V shared across heads).
// Grid: (S/64, H, B). Block: 256 threads (16x16), each thread owns a 4x4
// patch of the 64x64 score tile / 64(row)x64(d) output tile.
// ---------------------------------------------------------------------------
#define SPAD 65
#define QTILE 64

__global__ __launch_bounds__(256) void flash_mqa(
    const float* __restrict__ Qg, const float* __restrict__ Kg,
    const float* __restrict__ Vg, float* __restrict__ out)
{
    extern __shared__ float sm[];
    float* Qs = sm;                   // [d][row]   (transposed, pre-scaled)
    float* Ks = sm + 64 * SPAD;       // [d][key]   (transposed)
    float* Vs = sm + 2 * 64 * SPAD;   // [key][d]
    float* Ps = sm + 3 * 64 * SPAD;   // [row][key]

    const int tid = threadIdx.x;
    const int tx = tid & 15;
    const int ty = tid >> 4;
    const int q0 = blockIdx.x * QTILE;
    const int h  = blockIdx.y;
    const int b  = blockIdx.z;
    const float scale = 0.125f;       // 1/sqrt(64)

    // Load Q tile (transposed into smem, pre-scaled)
    for (int e = tid; e < 64 * 64; e += 256) {
        int r = e >> 6, d = e & 63;
        Qs[d * SPAD + r] =
            Qg[((size_t)(b * SEQ + q0 + r)) * EMB + h * HDIM + d] * scale;
    }

    float m[4], l[4], o[4][4];
#pragma unroll
    for (int i = 0; i < 4; i++) {
        m[i] = -CUDART_INF_F;
        l[i] = 0.0f;
#pragma unroll
        for (int j = 0; j < 4; j++) o[i][j] = 0.0f;
    }

    const int ktmax = q0 / 64;   // causal: only tiles with keys <= q0+63
    for (int kt = 0; kt <= ktmax; kt++) {
        __syncthreads();   // previous iteration's Vs/Ps consumers done
        const int k0 = kt * 64;
        for (int e = tid; e < 64 * 64; e += 256) {
            int r = e >> 6, d = e & 63;
            float kval = Kg[((size_t)(b * SEQ + k0 + r)) * HDIM + d];
            float vval = Vg[((size_t)(b * SEQ + k0 + r)) * HDIM + d];
            Ks[d * SPAD + r] = kval;
            Vs[r * SPAD + d] = vval;
        }
        __syncthreads();

        // S = Q K^T (scaled)
        float s[4][4];
#pragma unroll
        for (int i = 0; i < 4; i++)
#pragma unroll
            for (int j = 0; j < 4; j++) s[i][j] = 0.0f;

        for (int d = 0; d < 64; d++) {
            float a[4], kk[4];
#pragma unroll
            for (int i = 0; i < 4; i++) a[i] = Qs[d * SPAD + ty * 4 + i];
#pragma unroll
            for (int j = 0; j < 4; j++) kk[j] = Ks[d * SPAD + tx * 4 + j];
#pragma unroll
            for (int i = 0; i < 4; i++)
#pragma unroll
                for (int j = 0; j < 4; j++) s[i][j] = fmaf(a[i], kk[j], s[i][j]);
        }

        // Causal mask on the diagonal tile
        if (kt == ktmax) {
#pragma unroll
            for (int i = 0; i < 4; i++) {
                int q = q0 + ty * 4 + i;
#pragma unroll
                for (int j = 0; j < 4; j++) {
                    int kx = k0 + tx * 4 + j;
                    if (kx > q) s[i][j] = -CUDART_INF_F;
                }
            }
        }

        // Row max (local 4, then across the 16 tx lanes)
        float mloc[4];
#pragma unroll
        for (int i = 0; i < 4; i++) {
            mloc[i] = fmaxf(fmaxf(s[i][0], s[i][1]), fmaxf(s[i][2], s[i][3]));
        }
#pragma unroll
        for (int off = 8; off >= 1; off >>= 1) {
#pragma unroll
            for (int i = 0; i < 4; i++)
                mloc[i] = fmaxf(mloc[i], __shfl_xor_sync(0xffffffffu, mloc[i], off, 16));
        }

        float mnew[4], corr[4];
#pragma unroll
        for (int i = 0; i < 4; i++) {
            mnew[i] = fmaxf(m[i], mloc[i]);
            corr[i] = __expf(m[i] - mnew[i]);   // 0 when m==-inf
            m[i] = mnew[i];
        }

        // P = exp(S - m), partial row sums
        float p[4][4], lloc[4];
#pragma unroll
        for (int i = 0; i < 4; i++) {
            lloc[i] = 0.0f;
#pragma unroll
            for (int j = 0; j < 4; j++) {
                p[i][j] = __expf(s[i][j] - mnew[i]);
                lloc[i] += p[i][j];
            }
        }
#pragma unroll
        for (int off = 8; off >= 1; off >>= 1) {
#pragma unroll
            for (int i = 0; i < 4; i++)
                lloc[i] += __shfl_xor_sync(0xffffffffu, lloc[i], off, 16);
        }
#pragma unroll
        for (int i = 0; i < 4; i++) {
            l[i] = l[i] * corr[i] + lloc[i];
#pragma unroll
            for (int j = 0; j < 4; j++) o[i][j] *= corr[i];
        }

        // Stage P to smem for the PV product
#pragma unroll
        for (int i = 0; i < 4; i++)
#pragma unroll
            for (int j = 0; j < 4; j++)
                Ps[(ty * 4 + i) * SPAD + tx * 4 + j] = p[i][j];
        __syncthreads();

        // O += P @ V
        for (int j = 0; j < 64; j++) {
            float vv[4], pp[4];
#pragma unroll
            for (int d = 0; d < 4; d++) vv[d] = Vs[j * SPAD + tx * 4 + d];
#pragma unroll
            for (int i = 0; i < 4; i++) pp[i] = Ps[(ty * 4 + i) * SPAD + j];
#pragma unroll
            for (int i = 0; i < 4; i++)
#pragma unroll
                for (int d = 0; d < 4; d++) o[i][d] = fmaf(pp[i], vv[d], o[i][d]);
        }
    }

    // Epilogue: normalize and write out[b, q, h*D + d]
#pragma unroll
    for (int i = 0; i < 4; i++) {
        float inv = 1.0f / l[i];
        int q = q0 + ty * 4 + i;
        size_t base = ((size_t)(b * SEQ + q)) * EMB + h * HDIM + tx * 4;
#pragma unroll
        for (int j = 0; j < 4; j++) out[base + j] = o[i][j] * inv;
    }
}

// ---------------------------------------------------------------------------
// Launch
// ---------------------------------------------------------------------------
extern "C" void kernel_launch(void* const* d_in, const int* in_sizes, int n_in,
                              void* d_out, int out_size)
{
    const float* X  = (const float*)d_in[0];   // [B,S,E]
    const float* Wq = (const float*)d_in[1];   // [E,E]
    const float* Wk = (const float*)d_in[2];   // [E,D]
    const float* Wv = (const float*)d_in[3];   // [E,D]
    float* out = (float*)d_out;

    float *Qbuf, *Kbuf, *Vbuf;
    cudaGetSymbolAddress((void**)&Qbuf, g_Q);
    cudaGetSymbolAddress((void**)&Kbuf, g_K);
    cudaGetSymbolAddress((void**)&Vbuf, g_V);

    // Projections: rows = B*S = 4096
    {
        dim3 blk(256);
        dim3 gq(EMB / 64, ROWS / 64);    // (16, 64)
        sgemm64<<<gq, blk>>>(X, Wq, Qbuf, ROWS, EMB, EMB);
        dim3 gk(HDIM / 64, ROWS / 64);   // (1, 64)
        sgemm64<<<gk, blk>>>(X, Wk, Kbuf, ROWS, HDIM, EMB);
        sgemm64<<<gk, blk>>>(X, Wv, Vbuf, ROWS, HDIM, EMB);
    }

    // Attention
    {
        const int smem = 4 * 64 * SPAD * (int)sizeof(float);  // 66,560 B
        cudaFuncSetAttribute(flash_mqa, cudaFuncAttributeMaxDynamicSharedMemorySize, smem);
        dim3 blk(256);
        dim3 grid(SEQ / QTILE, HEADS, BATCH);                 // (32, 16, 2)
        flash_mqa<<<grid, blk, smem>>>(Qbuf, Kbuf, Vbuf, out);
    }
}